// round 10
// baseline (speedup 1.0000x reference)
#include <cuda_runtime.h>
#include <cuda_bf16.h>

#define N_NODES 100000
#define N_EDGES 1600000
#define F_IN 128
#define N_H 3
#define N_D 16
#define HD 48
#define NEG_SLOPE 0.2f

#define SCAN_B 256
#define NB ((N_NODES + SCAN_B - 1) / SCAN_B)   // 391

#define GB_NODES 128          // nodes per gemm block
#define GB_THREADS 256

// Scratch (device globals)
__device__ float  g_feat[N_NODES * HD];     // projected features (N,48)
__device__ float4 g_el[N_NODES];            // (el0,el1,el2,_)
__device__ float4 g_er[N_NODES];            // (er0,er1,er2,_)
__device__ float4 g_edge[N_EDGES];          // packed (src_as_float, x0, x1, x2), grouped by dst
__device__ int    g_count[N_NODES];         // in-degree
__device__ int    g_off[N_NODES];           // CSR segment start
__device__ int    g_cur[N_NODES];           // scatter cursor
__device__ int    g_bsum[NB];               // per-block count sums
__device__ int    g_bbase[NB];              // exclusive scan of block sums

// ---------------------------------------------------------------------------
// Kernel 0: zero degree counters
// ---------------------------------------------------------------------------
__global__ void k_init() {
    int i = blockIdx.x * blockDim.x + threadIdx.x;
    if (i < N_NODES) g_count[i] = 0;
}

// ---------------------------------------------------------------------------
// Kernel 1: register-tiled GEMM. Block computes 128 nodes x 48 cols.
// Thread tile: 4 nodes x 6 cols = 24 accums; per k-step 10 scalar LDS feed
// 24 FFMA (vs 1 LDS.128 per 4 FFMA before -> ~10x less smem wavefront load).
// ---------------------------------------------------------------------------
__global__ __launch_bounds__(GB_THREADS) void k_gemm(const float* __restrict__ x,
                                                     const float* __restrict__ W)
{
    __shared__ float Wt[F_IN][HD];        // Wt[k][j] = W[j*F_IN + k], 24KB
    __shared__ float Xs[16][GB_NODES];    // one k-chunk of x, 8KB

    int tid = threadIdx.x;
    for (int i = tid; i < HD * F_IN; i += GB_THREADS) {
        int j = i / F_IN, k = i % F_IN;
        Wt[k][j] = W[i];
    }

    int node_base = blockIdx.x * GB_NODES;
    int ng = tid >> 3;            // node group 0..31 (4 nodes each)
    int cg = tid & 7;             // col group 0..7 (6 cols each)
    int ng4 = ng * 4;
    int cg6 = cg * 6;

    // x loader mapping: thread -> (node ln, k-offset lk)
    int ln = tid & 127;
    int lk = (tid >> 7) * 8;
    int gnode = node_base + ln;
    bool ldok = (gnode < N_NODES);
    const float* xrow = x + (size_t)gnode * F_IN + lk;

    float acc[4][6];
#pragma unroll
    for (int i = 0; i < 4; i++)
#pragma unroll
        for (int c = 0; c < 6; c++) acc[i][c] = 0.f;

    for (int kk = 0; kk < F_IN; kk += 16) {
        __syncthreads();
        float4 v0 = ldok ? *(const float4*)(xrow + kk)     : make_float4(0.f,0.f,0.f,0.f);
        float4 v1 = ldok ? *(const float4*)(xrow + kk + 4) : make_float4(0.f,0.f,0.f,0.f);
        Xs[lk + 0][ln] = v0.x; Xs[lk + 1][ln] = v0.y;
        Xs[lk + 2][ln] = v0.z; Xs[lk + 3][ln] = v0.w;
        Xs[lk + 4][ln] = v1.x; Xs[lk + 5][ln] = v1.y;
        Xs[lk + 6][ln] = v1.z; Xs[lk + 7][ln] = v1.w;
        __syncthreads();

#pragma unroll
        for (int k = 0; k < 16; k++) {
            float a0 = Xs[k][ng4 + 0];
            float a1 = Xs[k][ng4 + 1];
            float a2 = Xs[k][ng4 + 2];
            float a3 = Xs[k][ng4 + 3];
            const float* wr = &Wt[kk + k][cg6];
            float w0 = wr[0], w1 = wr[1], w2 = wr[2];
            float w3 = wr[3], w4 = wr[4], w5 = wr[5];
            acc[0][0] = fmaf(a0, w0, acc[0][0]); acc[0][1] = fmaf(a0, w1, acc[0][1]);
            acc[0][2] = fmaf(a0, w2, acc[0][2]); acc[0][3] = fmaf(a0, w3, acc[0][3]);
            acc[0][4] = fmaf(a0, w4, acc[0][4]); acc[0][5] = fmaf(a0, w5, acc[0][5]);
            acc[1][0] = fmaf(a1, w0, acc[1][0]); acc[1][1] = fmaf(a1, w1, acc[1][1]);
            acc[1][2] = fmaf(a1, w2, acc[1][2]); acc[1][3] = fmaf(a1, w3, acc[1][3]);
            acc[1][4] = fmaf(a1, w4, acc[1][4]); acc[1][5] = fmaf(a1, w5, acc[1][5]);
            acc[2][0] = fmaf(a2, w0, acc[2][0]); acc[2][1] = fmaf(a2, w1, acc[2][1]);
            acc[2][2] = fmaf(a2, w2, acc[2][2]); acc[2][3] = fmaf(a2, w3, acc[2][3]);
            acc[2][4] = fmaf(a2, w4, acc[2][4]); acc[2][5] = fmaf(a2, w5, acc[2][5]);
            acc[3][0] = fmaf(a3, w0, acc[3][0]); acc[3][1] = fmaf(a3, w1, acc[3][1]);
            acc[3][2] = fmaf(a3, w2, acc[3][2]); acc[3][3] = fmaf(a3, w3, acc[3][3]);
            acc[3][4] = fmaf(a3, w4, acc[3][4]); acc[3][5] = fmaf(a3, w5, acc[3][5]);
        }
    }

    // store 4 nodes x 6 cols (float2 x3 per node)
#pragma unroll
    for (int i = 0; i < 4; i++) {
        int n = node_base + ng4 + i;
        if (n < N_NODES) {
            float* dstp = g_feat + (size_t)n * HD + cg6;
            *(float2*)(dstp + 0) = make_float2(acc[i][0], acc[i][1]);
            *(float2*)(dstp + 2) = make_float2(acc[i][2], acc[i][3]);
            *(float2*)(dstp + 4) = make_float2(acc[i][4], acc[i][5]);
        }
    }
}

// ---------------------------------------------------------------------------
// Kernel 1b: attention logits el/er per node (reads freshly-written g_feat).
// ---------------------------------------------------------------------------
__global__ __launch_bounds__(256) void k_logits(const float* __restrict__ al,
                                                const float* __restrict__ ar)
{
    __shared__ float als[HD], ars[HD];
    if (threadIdx.x < HD) {
        als[threadIdx.x] = al[threadIdx.x];
        ars[threadIdx.x] = ar[threadIdx.x];
    }
    __syncthreads();

    int n = blockIdx.x * 256 + threadIdx.x;
    if (n >= N_NODES) return;

    const float4* f4 = (const float4*)(g_feat + (size_t)n * HD);
    float el[N_H] = {0.f, 0.f, 0.f};
    float er[N_H] = {0.f, 0.f, 0.f};
#pragma unroll
    for (int q = 0; q < HD / 4; q++) {
        float4 f = f4[q];
        int j = 4 * q;
        int h = j >> 4;   // 4 consecutive cols never cross a 16-col head boundary
        el[h] = fmaf(f.x, als[j], fmaf(f.y, als[j+1], fmaf(f.z, als[j+2], fmaf(f.w, als[j+3], el[h]))));
        er[h] = fmaf(f.x, ars[j], fmaf(f.y, ars[j+1], fmaf(f.z, ars[j+2], fmaf(f.w, ars[j+3], er[h]))));
    }
    g_el[n] = make_float4(el[0], el[1], el[2], 0.f);
    g_er[n] = make_float4(er[0], er[1], er[2], 0.f);
}

// ---------------------------------------------------------------------------
// Kernel 2: in-degree histogram
// ---------------------------------------------------------------------------
__global__ void k_hist(const int* __restrict__ dst) {
    int e = blockIdx.x * blockDim.x + threadIdx.x;
    if (e >= N_EDGES) return;
    atomicAdd(&g_count[dst[e]], 1);
}

// ---------------------------------------------------------------------------
// Kernel 3a/3b/3c: hierarchical exclusive scan of g_count -> g_off, g_cur
// ---------------------------------------------------------------------------
__global__ __launch_bounds__(SCAN_B) void k_bsum() {
    __shared__ int sh[SCAN_B];
    int i = blockIdx.x * SCAN_B + threadIdx.x;
    sh[threadIdx.x] = (i < N_NODES) ? g_count[i] : 0;
    __syncthreads();
    for (int off = SCAN_B / 2; off > 0; off >>= 1) {
        if (threadIdx.x < off) sh[threadIdx.x] += sh[threadIdx.x + off];
        __syncthreads();
    }
    if (threadIdx.x == 0) g_bsum[blockIdx.x] = sh[0];
}

__global__ __launch_bounds__(512) void k_sscan() {
    __shared__ int sh[512];
    int t = threadIdx.x;
    sh[t] = (t < NB) ? g_bsum[t] : 0;
    __syncthreads();
    for (int off = 1; off < 512; off <<= 1) {
        int v = (t >= off) ? sh[t - off] : 0;
        __syncthreads();
        sh[t] += v;
        __syncthreads();
    }
    if (t < NB) g_bbase[t] = (t == 0) ? 0 : sh[t - 1];
}

__global__ __launch_bounds__(SCAN_B) void k_off() {
    __shared__ int sh[SCAN_B];
    int i = blockIdx.x * SCAN_B + threadIdx.x;
    int t = threadIdx.x;
    int c = (i < N_NODES) ? g_count[i] : 0;
    sh[t] = c;
    __syncthreads();
    for (int off = 1; off < SCAN_B; off <<= 1) {
        int v = (t >= off) ? sh[t - off] : 0;
        __syncthreads();
        sh[t] += v;
        __syncthreads();
    }
    if (i < N_NODES) {
        int excl = g_bbase[blockIdx.x] + sh[t] - c;
        g_off[i] = excl;
        g_cur[i] = excl;
    }
}

// ---------------------------------------------------------------------------
// Kernel 4: edge scatter (R5 one-edge form).
// Max-subtraction skipped: |e| <= ~4, softmax shift-invariant (fp32-safe).
// ---------------------------------------------------------------------------
__global__ void k_scatter(const int* __restrict__ src, const int* __restrict__ dst) {
    int e = blockIdx.x * blockDim.x + threadIdx.x;
    if (e >= N_EDGES) return;
    int s = src[e], d = dst[e];
    float4 L = g_el[s];
    float4 R = g_er[d];
    float v0 = L.x + R.x, v1 = L.y + R.y, v2 = L.z + R.z;
    v0 = v0 > 0.f ? v0 : NEG_SLOPE * v0;
    v1 = v1 > 0.f ? v1 : NEG_SLOPE * v1;
    v2 = v2 > 0.f ? v2 : NEG_SLOPE * v2;
    float x0 = __expf(v0), x1 = __expf(v1), x2 = __expf(v2);
    int pos = atomicAdd(&g_cur[d], 1);
    g_edge[pos] = make_float4(__int_as_float(s), x0, x1, x2);
}

// ---------------------------------------------------------------------------
// Kernel 5: per-dst aggregation, 48 threads/node, 2-edge unroll (R5 config).
// ---------------------------------------------------------------------------
__global__ __launch_bounds__(192) void k_agg(const float* __restrict__ lin,
                                             float* __restrict__ out) {
    int d = blockIdx.x * 4 + threadIdx.y;
    if (d >= N_NODES) return;
    int c = threadIdx.x;        // 0..47
    int h = c >> 4;             // head index 0..2

    int beg = g_off[d];
    int cnt = g_count[d];
    int end = beg + cnt;

    float num0 = 0.f, den0 = 0.f, num1 = 0.f, den1 = 0.f;
    int p = beg;
    for (; p + 2 <= end; p += 2) {
        float4 pk0 = g_edge[p];
        float4 pk1 = g_edge[p + 1];
        int s0 = __float_as_int(pk0.x);
        int s1 = __float_as_int(pk1.x);
        float a0 = (h == 0) ? pk0.y : ((h == 1) ? pk0.z : pk0.w);
        float a1 = (h == 0) ? pk1.y : ((h == 1) ? pk1.z : pk1.w);
        float f0 = __ldg(&g_feat[s0 * HD + c]);
        float f1 = __ldg(&g_feat[s1 * HD + c]);
        num0 = fmaf(a0, f0, num0); den0 += a0;
        num1 = fmaf(a1, f1, num1); den1 += a1;
    }
    if (p < end) {
        float4 pk = g_edge[p];
        int s = __float_as_int(pk.x);
        float a = (h == 0) ? pk.y : ((h == 1) ? pk.z : pk.w);
        float f = __ldg(&g_feat[s * HD + c]);
        num0 = fmaf(a, f, num0); den0 += a;
    }
    float num = num0 + num1, den = den0 + den1;
    float msg = (cnt > 0) ? (num / den) : 0.f;
    float l = lin[d];
    float fd = g_feat[d * HD + c];
    out[d * HD + c] = (1.f - l) * msg + l * fd;
}

// ---------------------------------------------------------------------------
// Launch order keeps k_gemm in profile slot 4 (ncu captures the 4th launch).
// ---------------------------------------------------------------------------
extern "C" void kernel_launch(void* const* d_in, const int* in_sizes, int n_in,
                              void* d_out, int out_size) {
    const float* x   = (const float*)d_in[0];
    const float* W   = (const float*)d_in[1];
    const float* al  = (const float*)d_in[2];
    const float* ar  = (const float*)d_in[3];
    const float* lin = (const float*)d_in[4];
    const int*   src = (const int*)d_in[5];
    const int*   dst = (const int*)d_in[6];
    float* out = (float*)d_out;

    k_init<<<(N_NODES + 255) / 256, 256>>>();
    k_hist<<<(N_EDGES + 255) / 256, 256>>>(dst);
    k_bsum<<<NB, SCAN_B>>>();
    k_gemm<<<(N_NODES + GB_NODES - 1) / GB_NODES, GB_THREADS>>>(x, W);  // slot 4
    k_logits<<<(N_NODES + 255) / 256, 256>>>(al, ar);
    k_sscan<<<1, 512>>>();
    k_off<<<NB, SCAN_B>>>();
    k_scatter<<<(N_EDGES + 255) / 256, 256>>>(src, dst);
    dim3 aggBlock(48, 4);
    k_agg<<<(N_NODES + 3) / 4, aggBlock>>>(lin, out);
}

// round 11
// speedup vs baseline: 1.0089x; 1.0089x over previous
#include <cuda_runtime.h>
#include <cuda_bf16.h>

#define N_NODES 100000
#define N_EDGES 1600000
#define F_IN 128
#define N_H 3
#define N_D 16
#define HD 48
#define NEG_SLOPE 0.2f

#define SCAN_B 256
#define NB ((N_NODES + SCAN_B - 1) / SCAN_B)   // 391

#define GB_NODES 128          // nodes per gemm block
#define GB_THREADS 256

// Scratch (device globals)
__device__ float  g_feat[N_NODES * HD];     // projected features (N,48)
__device__ float4 g_el[N_NODES];            // (el0,el1,el2,_)
__device__ float4 g_er[N_NODES];            // (er0,er1,er2,_)
__device__ float4 g_edge[N_EDGES];          // packed (src_as_float, x0, x1, x2), grouped by dst
__device__ int    g_count[N_NODES];         // in-degree
__device__ int    g_off[N_NODES];           // CSR segment start
__device__ int    g_cur[N_NODES];           // scatter cursor
__device__ int    g_bsum[NB];               // per-block count sums
__device__ int    g_bbase[NB];              // exclusive scan of block sums

// ---------------------------------------------------------------------------
// Kernel 0: zero degree counters
// ---------------------------------------------------------------------------
__global__ void k_init() {
    int i = blockIdx.x * blockDim.x + threadIdx.x;
    if (i < N_NODES) g_count[i] = 0;
}

// ---------------------------------------------------------------------------
// Kernel 1: register-tiled GEMM, vectorized SMEM reads.
// Thread tile 4 nodes x 6 cols; per k-step: 1 LDS.128 (Xs) + 3 LDS.64 (Wt)
// feed 24 FFMA  (was 10 scalar LDS -> L1-bound at 66%).
// ---------------------------------------------------------------------------
__global__ __launch_bounds__(GB_THREADS) void k_gemm(const float* __restrict__ x,
                                                     const float* __restrict__ W)
{
    __shared__ __align__(16) float Wt[F_IN][HD];      // Wt[k][j] = W[j*F_IN+k]
    __shared__ __align__(16) float Xs[16][GB_NODES];  // one k-chunk of x

    int tid = threadIdx.x;
    for (int i = tid; i < HD * F_IN; i += GB_THREADS) {
        int j = i / F_IN, k = i % F_IN;
        Wt[k][j] = W[i];
    }

    int node_base = blockIdx.x * GB_NODES;
    int ng = tid >> 3;            // node group 0..31 (4 nodes each)
    int cg = tid & 7;             // col group 0..7 (6 cols each)
    int ng4 = ng * 4;
    int cg6 = cg * 6;

    // x loader mapping: thread -> (node ln, k-offset lk)
    int ln = tid & 127;
    int lk = (tid >> 7) * 8;
    int gnode = node_base + ln;
    bool ldok = (gnode < N_NODES);
    const float* xrow = x + (size_t)gnode * F_IN + lk;

    float acc[4][6];
#pragma unroll
    for (int i = 0; i < 4; i++)
#pragma unroll
        for (int c = 0; c < 6; c++) acc[i][c] = 0.f;

    for (int kk = 0; kk < F_IN; kk += 16) {
        __syncthreads();
        float4 v0 = ldok ? *(const float4*)(xrow + kk)     : make_float4(0.f,0.f,0.f,0.f);
        float4 v1 = ldok ? *(const float4*)(xrow + kk + 4) : make_float4(0.f,0.f,0.f,0.f);
        Xs[lk + 0][ln] = v0.x; Xs[lk + 1][ln] = v0.y;
        Xs[lk + 2][ln] = v0.z; Xs[lk + 3][ln] = v0.w;
        Xs[lk + 4][ln] = v1.x; Xs[lk + 5][ln] = v1.y;
        Xs[lk + 6][ln] = v1.z; Xs[lk + 7][ln] = v1.w;
        __syncthreads();

#pragma unroll
        for (int k = 0; k < 16; k++) {
            float4 a = *(const float4*)&Xs[k][ng4];            // LDS.128, bcast
            const float2* wr = (const float2*)&Wt[kk + k][cg6];
            float2 w01 = wr[0];                                 // LDS.64 x3
            float2 w23 = wr[1];
            float2 w45 = wr[2];
            acc[0][0] = fmaf(a.x, w01.x, acc[0][0]); acc[0][1] = fmaf(a.x, w01.y, acc[0][1]);
            acc[0][2] = fmaf(a.x, w23.x, acc[0][2]); acc[0][3] = fmaf(a.x, w23.y, acc[0][3]);
            acc[0][4] = fmaf(a.x, w45.x, acc[0][4]); acc[0][5] = fmaf(a.x, w45.y, acc[0][5]);
            acc[1][0] = fmaf(a.y, w01.x, acc[1][0]); acc[1][1] = fmaf(a.y, w01.y, acc[1][1]);
            acc[1][2] = fmaf(a.y, w23.x, acc[1][2]); acc[1][3] = fmaf(a.y, w23.y, acc[1][3]);
            acc[1][4] = fmaf(a.y, w45.x, acc[1][4]); acc[1][5] = fmaf(a.y, w45.y, acc[1][5]);
            acc[2][0] = fmaf(a.z, w01.x, acc[2][0]); acc[2][1] = fmaf(a.z, w01.y, acc[2][1]);
            acc[2][2] = fmaf(a.z, w23.x, acc[2][2]); acc[2][3] = fmaf(a.z, w23.y, acc[2][3]);
            acc[2][4] = fmaf(a.z, w45.x, acc[2][4]); acc[2][5] = fmaf(a.z, w45.y, acc[2][5]);
            acc[3][0] = fmaf(a.w, w01.x, acc[3][0]); acc[3][1] = fmaf(a.w, w01.y, acc[3][1]);
            acc[3][2] = fmaf(a.w, w23.x, acc[3][2]); acc[3][3] = fmaf(a.w, w23.y, acc[3][3]);
            acc[3][4] = fmaf(a.w, w45.x, acc[3][4]); acc[3][5] = fmaf(a.w, w45.y, acc[3][5]);
        }
    }

    // store 4 nodes x 6 cols (float2 x3 per node)
#pragma unroll
    for (int i = 0; i < 4; i++) {
        int n = node_base + ng4 + i;
        if (n < N_NODES) {
            float* dstp = g_feat + (size_t)n * HD + cg6;
            *(float2*)(dstp + 0) = make_float2(acc[i][0], acc[i][1]);
            *(float2*)(dstp + 2) = make_float2(acc[i][2], acc[i][3]);
            *(float2*)(dstp + 4) = make_float2(acc[i][4], acc[i][5]);
        }
    }
}

// ---------------------------------------------------------------------------
// Kernel 1b: attention logits el/er per node (reads freshly-written g_feat).
// ---------------------------------------------------------------------------
__global__ __launch_bounds__(256) void k_logits(const float* __restrict__ al,
                                                const float* __restrict__ ar)
{
    __shared__ float als[HD], ars[HD];
    if (threadIdx.x < HD) {
        als[threadIdx.x] = al[threadIdx.x];
        ars[threadIdx.x] = ar[threadIdx.x];
    }
    __syncthreads();

    int n = blockIdx.x * 256 + threadIdx.x;
    if (n >= N_NODES) return;

    const float4* f4 = (const float4*)(g_feat + (size_t)n * HD);
    float el[N_H] = {0.f, 0.f, 0.f};
    float er[N_H] = {0.f, 0.f, 0.f};
#pragma unroll
    for (int q = 0; q < HD / 4; q++) {
        float4 f = f4[q];
        int j = 4 * q;
        int h = j >> 4;   // 4 consecutive cols never cross a 16-col head boundary
        el[h] = fmaf(f.x, als[j], fmaf(f.y, als[j+1], fmaf(f.z, als[j+2], fmaf(f.w, als[j+3], el[h]))));
        er[h] = fmaf(f.x, ars[j], fmaf(f.y, ars[j+1], fmaf(f.z, ars[j+2], fmaf(f.w, ars[j+3], er[h]))));
    }
    g_el[n] = make_float4(el[0], el[1], el[2], 0.f);
    g_er[n] = make_float4(er[0], er[1], er[2], 0.f);
}

// ---------------------------------------------------------------------------
// Kernel 2: in-degree histogram
// ---------------------------------------------------------------------------
__global__ void k_hist(const int* __restrict__ dst) {
    int e = blockIdx.x * blockDim.x + threadIdx.x;
    if (e >= N_EDGES) return;
    atomicAdd(&g_count[dst[e]], 1);
}

// ---------------------------------------------------------------------------
// Kernel 3a/3b/3c: hierarchical exclusive scan of g_count -> g_off, g_cur
// ---------------------------------------------------------------------------
__global__ __launch_bounds__(SCAN_B) void k_bsum() {
    __shared__ int sh[SCAN_B];
    int i = blockIdx.x * SCAN_B + threadIdx.x;
    sh[threadIdx.x] = (i < N_NODES) ? g_count[i] : 0;
    __syncthreads();
    for (int off = SCAN_B / 2; off > 0; off >>= 1) {
        if (threadIdx.x < off) sh[threadIdx.x] += sh[threadIdx.x + off];
        __syncthreads();
    }
    if (threadIdx.x == 0) g_bsum[blockIdx.x] = sh[0];
}

__global__ __launch_bounds__(512) void k_sscan() {
    __shared__ int sh[512];
    int t = threadIdx.x;
    sh[t] = (t < NB) ? g_bsum[t] : 0;
    __syncthreads();
    for (int off = 1; off < 512; off <<= 1) {
        int v = (t >= off) ? sh[t - off] : 0;
        __syncthreads();
        sh[t] += v;
        __syncthreads();
    }
    if (t < NB) g_bbase[t] = (t == 0) ? 0 : sh[t - 1];
}

__global__ __launch_bounds__(SCAN_B) void k_off() {
    __shared__ int sh[SCAN_B];
    int i = blockIdx.x * SCAN_B + threadIdx.x;
    int t = threadIdx.x;
    int c = (i < N_NODES) ? g_count[i] : 0;
    sh[t] = c;
    __syncthreads();
    for (int off = 1; off < SCAN_B; off <<= 1) {
        int v = (t >= off) ? sh[t - off] : 0;
        __syncthreads();
        sh[t] += v;
        __syncthreads();
    }
    if (i < N_NODES) {
        int excl = g_bbase[blockIdx.x] + sh[t] - c;
        g_off[i] = excl;
        g_cur[i] = excl;
    }
}

// ---------------------------------------------------------------------------
// Kernel 4: edge scatter (R5 one-edge form).
// Max-subtraction skipped: |e| <= ~4, softmax shift-invariant (fp32-safe).
// ---------------------------------------------------------------------------
__global__ void k_scatter(const int* __restrict__ src, const int* __restrict__ dst) {
    int e = blockIdx.x * blockDim.x + threadIdx.x;
    if (e >= N_EDGES) return;
    int s = src[e], d = dst[e];
    float4 L = g_el[s];
    float4 R = g_er[d];
    float v0 = L.x + R.x, v1 = L.y + R.y, v2 = L.z + R.z;
    v0 = v0 > 0.f ? v0 : NEG_SLOPE * v0;
    v1 = v1 > 0.f ? v1 : NEG_SLOPE * v1;
    v2 = v2 > 0.f ? v2 : NEG_SLOPE * v2;
    float x0 = __expf(v0), x1 = __expf(v1), x2 = __expf(v2);
    int pos = atomicAdd(&g_cur[d], 1);
    g_edge[pos] = make_float4(__int_as_float(s), x0, x1, x2);
}

// ---------------------------------------------------------------------------
// Kernel 5: per-dst aggregation, 48 threads/node, 2-edge unroll (R5 config).
// ---------------------------------------------------------------------------
__global__ __launch_bounds__(192) void k_agg(const float* __restrict__ lin,
                                             float* __restrict__ out) {
    int d = blockIdx.x * 4 + threadIdx.y;
    if (d >= N_NODES) return;
    int c = threadIdx.x;        // 0..47
    int h = c >> 4;             // head index 0..2

    int beg = g_off[d];
    int cnt = g_count[d];
    int end = beg + cnt;

    float num0 = 0.f, den0 = 0.f, num1 = 0.f, den1 = 0.f;
    int p = beg;
    for (; p + 2 <= end; p += 2) {
        float4 pk0 = g_edge[p];
        float4 pk1 = g_edge[p + 1];
        int s0 = __float_as_int(pk0.x);
        int s1 = __float_as_int(pk1.x);
        float a0 = (h == 0) ? pk0.y : ((h == 1) ? pk0.z : pk0.w);
        float a1 = (h == 0) ? pk1.y : ((h == 1) ? pk1.z : pk1.w);
        float f0 = __ldg(&g_feat[s0 * HD + c]);
        float f1 = __ldg(&g_feat[s1 * HD + c]);
        num0 = fmaf(a0, f0, num0); den0 += a0;
        num1 = fmaf(a1, f1, num1); den1 += a1;
    }
    if (p < end) {
        float4 pk = g_edge[p];
        int s = __float_as_int(pk.x);
        float a = (h == 0) ? pk.y : ((h == 1) ? pk.z : pk.w);
        float f = __ldg(&g_feat[s * HD + c]);
        num0 = fmaf(a, f, num0); den0 += a;
    }
    float num = num0 + num1, den = den0 + den1;
    float msg = (cnt > 0) ? (num / den) : 0.f;
    float l = lin[d];
    float fd = g_feat[d * HD + c];
    out[d * HD + c] = (1.f - l) * msg + l * fd;
}

// ---------------------------------------------------------------------------
// R5 launch order (gemm early) to remove the reorder variable.
// ---------------------------------------------------------------------------
extern "C" void kernel_launch(void* const* d_in, const int* in_sizes, int n_in,
                              void* d_out, int out_size) {
    const float* x   = (const float*)d_in[0];
    const float* W   = (const float*)d_in[1];
    const float* al  = (const float*)d_in[2];
    const float* ar  = (const float*)d_in[3];
    const float* lin = (const float*)d_in[4];
    const int*   src = (const int*)d_in[5];
    const int*   dst = (const int*)d_in[6];
    float* out = (float*)d_out;

    k_init<<<(N_NODES + 255) / 256, 256>>>();
    k_gemm<<<(N_NODES + GB_NODES - 1) / GB_NODES, GB_THREADS>>>(x, W);
    k_logits<<<(N_NODES + 255) / 256, 256>>>(al, ar);
    k_hist<<<(N_EDGES + 255) / 256, 256>>>(dst);
    k_bsum<<<NB, SCAN_B>>>();
    k_sscan<<<1, 512>>>();
    k_off<<<NB, SCAN_B>>>();
    k_scatter<<<(N_EDGES + 255) / 256, 256>>>(src, dst);
    dim3 aggBlock(48, 4);
    k_agg<<<(N_NODES + 3) / 4, aggBlock>>>(lin, out);
}

// round 12
// speedup vs baseline: 1.2510x; 1.2401x over previous
#include <cuda_runtime.h>
#include <cuda_bf16.h>

#define N_NODES 100000
#define N_EDGES 1600000
#define F_IN 128
#define N_H 3
#define N_D 16
#define HD 48
#define NEG_SLOPE 0.2f

#define SCAN_B 256
#define NB ((N_NODES + SCAN_B - 1) / SCAN_B)   // 391

#define GB_NODES 128          // nodes per gemm block
#define GB_THREADS 256

// Scratch (device globals)
__device__ float  g_feat[N_NODES * HD];     // projected features (N,48)
__device__ float4 g_el[N_NODES];            // (el0,el1,el2,_)
__device__ float4 g_er[N_NODES];            // (er0,er1,er2,_)
__device__ float4 g_edge[N_EDGES];          // packed (src_as_float, x0, x1, x2), grouped by dst
__device__ int    g_count[N_NODES];         // in-degree
__device__ int    g_off[N_NODES];           // CSR segment start
__device__ int    g_cur[N_NODES];           // scatter cursor
__device__ int    g_bsum[NB];               // per-block count sums
__device__ int    g_bbase[NB];              // exclusive scan of block sums

// ---------------------------------------------------------------------------
// Kernel 0: zero degree counters
// ---------------------------------------------------------------------------
__global__ void k_init() {
    int i = blockIdx.x * blockDim.x + threadIdx.x;
    if (i < N_NODES) g_count[i] = 0;
}

// ---------------------------------------------------------------------------
// Kernel 1: register-tiled GEMM, vectorized SMEM reads (R10/R11 version).
// Thread tile 4 nodes x 6 cols; per k-step 1 LDS.128 + 3 LDS.64 feed 24 FFMA.
// ---------------------------------------------------------------------------
__global__ __launch_bounds__(GB_THREADS) void k_gemm(const float* __restrict__ x,
                                                     const float* __restrict__ W)
{
    __shared__ __align__(16) float Wt[F_IN][HD];      // Wt[k][j] = W[j*F_IN+k]
    __shared__ __align__(16) float Xs[16][GB_NODES];  // one k-chunk of x

    int tid = threadIdx.x;
    for (int i = tid; i < HD * F_IN; i += GB_THREADS) {
        int j = i / F_IN, k = i % F_IN;
        Wt[k][j] = W[i];
    }

    int node_base = blockIdx.x * GB_NODES;
    int ng = tid >> 3;            // node group 0..31 (4 nodes each)
    int cg = tid & 7;             // col group 0..7 (6 cols each)
    int ng4 = ng * 4;
    int cg6 = cg * 6;

    int ln = tid & 127;
    int lk = (tid >> 7) * 8;
    int gnode = node_base + ln;
    bool ldok = (gnode < N_NODES);
    const float* xrow = x + (size_t)gnode * F_IN + lk;

    float acc[4][6];
#pragma unroll
    for (int i = 0; i < 4; i++)
#pragma unroll
        for (int c = 0; c < 6; c++) acc[i][c] = 0.f;

    for (int kk = 0; kk < F_IN; kk += 16) {
        __syncthreads();
        float4 v0 = ldok ? *(const float4*)(xrow + kk)     : make_float4(0.f,0.f,0.f,0.f);
        float4 v1 = ldok ? *(const float4*)(xrow + kk + 4) : make_float4(0.f,0.f,0.f,0.f);
        Xs[lk + 0][ln] = v0.x; Xs[lk + 1][ln] = v0.y;
        Xs[lk + 2][ln] = v0.z; Xs[lk + 3][ln] = v0.w;
        Xs[lk + 4][ln] = v1.x; Xs[lk + 5][ln] = v1.y;
        Xs[lk + 6][ln] = v1.z; Xs[lk + 7][ln] = v1.w;
        __syncthreads();

#pragma unroll
        for (int k = 0; k < 16; k++) {
            float4 a = *(const float4*)&Xs[k][ng4];            // LDS.128, bcast
            const float2* wr = (const float2*)&Wt[kk + k][cg6];
            float2 w01 = wr[0];
            float2 w23 = wr[1];
            float2 w45 = wr[2];
            acc[0][0] = fmaf(a.x, w01.x, acc[0][0]); acc[0][1] = fmaf(a.x, w01.y, acc[0][1]);
            acc[0][2] = fmaf(a.x, w23.x, acc[0][2]); acc[0][3] = fmaf(a.x, w23.y, acc[0][3]);
            acc[0][4] = fmaf(a.x, w45.x, acc[0][4]); acc[0][5] = fmaf(a.x, w45.y, acc[0][5]);
            acc[1][0] = fmaf(a.y, w01.x, acc[1][0]); acc[1][1] = fmaf(a.y, w01.y, acc[1][1]);
            acc[1][2] = fmaf(a.y, w23.x, acc[1][2]); acc[1][3] = fmaf(a.y, w23.y, acc[1][3]);
            acc[1][4] = fmaf(a.y, w45.x, acc[1][4]); acc[1][5] = fmaf(a.y, w45.y, acc[1][5]);
            acc[2][0] = fmaf(a.z, w01.x, acc[2][0]); acc[2][1] = fmaf(a.z, w01.y, acc[2][1]);
            acc[2][2] = fmaf(a.z, w23.x, acc[2][2]); acc[2][3] = fmaf(a.z, w23.y, acc[2][3]);
            acc[2][4] = fmaf(a.z, w45.x, acc[2][4]); acc[2][5] = fmaf(a.z, w45.y, acc[2][5]);
            acc[3][0] = fmaf(a.w, w01.x, acc[3][0]); acc[3][1] = fmaf(a.w, w01.y, acc[3][1]);
            acc[3][2] = fmaf(a.w, w23.x, acc[3][2]); acc[3][3] = fmaf(a.w, w23.y, acc[3][3]);
            acc[3][4] = fmaf(a.w, w45.x, acc[3][4]); acc[3][5] = fmaf(a.w, w45.y, acc[3][5]);
        }
    }

#pragma unroll
    for (int i = 0; i < 4; i++) {
        int n = node_base + ng4 + i;
        if (n < N_NODES) {
            float* dstp = g_feat + (size_t)n * HD + cg6;
            *(float2*)(dstp + 0) = make_float2(acc[i][0], acc[i][1]);
            *(float2*)(dstp + 2) = make_float2(acc[i][2], acc[i][3]);
            *(float2*)(dstp + 4) = make_float2(acc[i][4], acc[i][5]);
        }
    }
}

// ---------------------------------------------------------------------------
// Kernel 1b: attention logits el/er per node (reads freshly-written g_feat).
// ---------------------------------------------------------------------------
__global__ __launch_bounds__(256) void k_logits(const float* __restrict__ al,
                                                const float* __restrict__ ar)
{
    __shared__ float als[HD], ars[HD];
    if (threadIdx.x < HD) {
        als[threadIdx.x] = al[threadIdx.x];
        ars[threadIdx.x] = ar[threadIdx.x];
    }
    __syncthreads();

    int n = blockIdx.x * 256 + threadIdx.x;
    if (n >= N_NODES) return;

    const float4* f4 = (const float4*)(g_feat + (size_t)n * HD);
    float el[N_H] = {0.f, 0.f, 0.f};
    float er[N_H] = {0.f, 0.f, 0.f};
#pragma unroll
    for (int q = 0; q < HD / 4; q++) {
        float4 f = f4[q];
        int j = 4 * q;
        int h = j >> 4;
        el[h] = fmaf(f.x, als[j], fmaf(f.y, als[j+1], fmaf(f.z, als[j+2], fmaf(f.w, als[j+3], el[h]))));
        er[h] = fmaf(f.x, ars[j], fmaf(f.y, ars[j+1], fmaf(f.z, ars[j+2], fmaf(f.w, ars[j+3], er[h]))));
    }
    g_el[n] = make_float4(el[0], el[1], el[2], 0.f);
    g_er[n] = make_float4(er[0], er[1], er[2], 0.f);
}

// ---------------------------------------------------------------------------
// Kernel 2: in-degree histogram
// ---------------------------------------------------------------------------
__global__ void k_hist(const int* __restrict__ dst) {
    int e = blockIdx.x * blockDim.x + threadIdx.x;
    if (e >= N_EDGES) return;
    atomicAdd(&g_count[dst[e]], 1);
}

// ---------------------------------------------------------------------------
// Kernel 3a/3b/3c: hierarchical exclusive scan of g_count -> g_off, g_cur
// ---------------------------------------------------------------------------
__global__ __launch_bounds__(SCAN_B) void k_bsum() {
    __shared__ int sh[SCAN_B];
    int i = blockIdx.x * SCAN_B + threadIdx.x;
    sh[threadIdx.x] = (i < N_NODES) ? g_count[i] : 0;
    __syncthreads();
    for (int off = SCAN_B / 2; off > 0; off >>= 1) {
        if (threadIdx.x < off) sh[threadIdx.x] += sh[threadIdx.x + off];
        __syncthreads();
    }
    if (threadIdx.x == 0) g_bsum[blockIdx.x] = sh[0];
}

__global__ __launch_bounds__(512) void k_sscan() {
    __shared__ int sh[512];
    int t = threadIdx.x;
    sh[t] = (t < NB) ? g_bsum[t] : 0;
    __syncthreads();
    for (int off = 1; off < 512; off <<= 1) {
        int v = (t >= off) ? sh[t - off] : 0;
        __syncthreads();
        sh[t] += v;
        __syncthreads();
    }
    if (t < NB) g_bbase[t] = (t == 0) ? 0 : sh[t - 1];
}

__global__ __launch_bounds__(SCAN_B) void k_off() {
    __shared__ int sh[SCAN_B];
    int i = blockIdx.x * SCAN_B + threadIdx.x;
    int t = threadIdx.x;
    int c = (i < N_NODES) ? g_count[i] : 0;
    sh[t] = c;
    __syncthreads();
    for (int off = 1; off < SCAN_B; off <<= 1) {
        int v = (t >= off) ? sh[t - off] : 0;
        __syncthreads();
        sh[t] += v;
        __syncthreads();
    }
    if (i < N_NODES) {
        int excl = g_bbase[blockIdx.x] + sh[t] - c;
        g_off[i] = excl;
        g_cur[i] = excl;
    }
}

// ---------------------------------------------------------------------------
// Kernel 4: edge scatter (one-edge form).
// Max-subtraction skipped: |e| <= ~4, softmax shift-invariant (fp32-safe).
// ---------------------------------------------------------------------------
__global__ void k_scatter(const int* __restrict__ src, const int* __restrict__ dst) {
    int e = blockIdx.x * blockDim.x + threadIdx.x;
    if (e >= N_EDGES) return;
    int s = src[e], d = dst[e];
    float4 L = g_el[s];
    float4 R = g_er[d];
    float v0 = L.x + R.x, v1 = L.y + R.y, v2 = L.z + R.z;
    v0 = v0 > 0.f ? v0 : NEG_SLOPE * v0;
    v1 = v1 > 0.f ? v1 : NEG_SLOPE * v1;
    v2 = v2 > 0.f ? v2 : NEG_SLOPE * v2;
    float x0 = __expf(v0), x1 = __expf(v1), x2 = __expf(v2);
    int pos = atomicAdd(&g_cur[d], 1);
    g_edge[pos] = make_float4(__int_as_float(s), x0, x1, x2);
}

// ---------------------------------------------------------------------------
// Kernel 5: per-dst aggregation, 12 threads/node with FLOAT4 gathers.
// Thread tx owns cols [4tx, 4tx+3]; a float4 never crosses a 16-col head
// boundary (head = tx>>2). Per edge per thread: 1 broadcast LDG.128 (payload)
// + 1 LDG.128 gather -> 4x fewer load instrs than scalar (48,4) version.
// 2-edge unroll keeps 4 independent LDG.128s in flight.
// ---------------------------------------------------------------------------
__global__ __launch_bounds__(192) void k_agg(const float* __restrict__ lin,
                                             float* __restrict__ out) {
    int d = blockIdx.x * 16 + threadIdx.y;
    if (d >= N_NODES) return;
    int tx = threadIdx.x;       // 0..11
    int c4 = tx * 4;            // col base 0,4,...,44
    int h = tx >> 2;            // head 0..2

    int beg = g_off[d];
    int cnt = g_count[d];
    int end = beg + cnt;

    float4 num0 = make_float4(0.f, 0.f, 0.f, 0.f);
    float4 num1 = make_float4(0.f, 0.f, 0.f, 0.f);
    float den0 = 0.f, den1 = 0.f;

    int p = beg;
    for (; p + 2 <= end; p += 2) {
        float4 pk0 = g_edge[p];
        float4 pk1 = g_edge[p + 1];
        int s0 = __float_as_int(pk0.x);
        int s1 = __float_as_int(pk1.x);
        float4 f0 = *(const float4*)(g_feat + (size_t)s0 * HD + c4);
        float4 f1 = *(const float4*)(g_feat + (size_t)s1 * HD + c4);
        float a0 = (h == 0) ? pk0.y : ((h == 1) ? pk0.z : pk0.w);
        float a1 = (h == 0) ? pk1.y : ((h == 1) ? pk1.z : pk1.w);
        num0.x = fmaf(a0, f0.x, num0.x); num0.y = fmaf(a0, f0.y, num0.y);
        num0.z = fmaf(a0, f0.z, num0.z); num0.w = fmaf(a0, f0.w, num0.w);
        den0 += a0;
        num1.x = fmaf(a1, f1.x, num1.x); num1.y = fmaf(a1, f1.y, num1.y);
        num1.z = fmaf(a1, f1.z, num1.z); num1.w = fmaf(a1, f1.w, num1.w);
        den1 += a1;
    }
    if (p < end) {
        float4 pk = g_edge[p];
        int s = __float_as_int(pk.x);
        float4 f = *(const float4*)(g_feat + (size_t)s * HD + c4);
        float a = (h == 0) ? pk.y : ((h == 1) ? pk.z : pk.w);
        num0.x = fmaf(a, f.x, num0.x); num0.y = fmaf(a, f.y, num0.y);
        num0.z = fmaf(a, f.z, num0.z); num0.w = fmaf(a, f.w, num0.w);
        den0 += a;
    }

    float den = den0 + den1;
    float inv = (cnt > 0) ? (1.f / den) : 0.f;
    float l = lin[d];
    float4 fd = *(const float4*)(g_feat + (size_t)d * HD + c4);
    float4 r;
    r.x = (1.f - l) * ((num0.x + num1.x) * inv) + l * fd.x;
    r.y = (1.f - l) * ((num0.y + num1.y) * inv) + l * fd.y;
    r.z = (1.f - l) * ((num0.z + num1.z) * inv) + l * fd.z;
    r.w = (1.f - l) * ((num0.w + num1.w) * inv) + l * fd.w;
    *(float4*)(out + (size_t)d * HD + c4) = r;
}

// ---------------------------------------------------------------------------
extern "C" void kernel_launch(void* const* d_in, const int* in_sizes, int n_in,
                              void* d_out, int out_size) {
    const float* x   = (const float*)d_in[0];
    const float* W   = (const float*)d_in[1];
    const float* al  = (const float*)d_in[2];
    const float* ar  = (const float*)d_in[3];
    const float* lin = (const float*)d_in[4];
    const int*   src = (const int*)d_in[5];
    const int*   dst = (const int*)d_in[6];
    float* out = (float*)d_out;

    k_init<<<(N_NODES + 255) / 256, 256>>>();
    k_gemm<<<(N_NODES + GB_NODES - 1) / GB_NODES, GB_THREADS>>>(x, W);
    k_logits<<<(N_NODES + 255) / 256, 256>>>(al, ar);
    k_hist<<<(N_EDGES + 255) / 256, 256>>>(dst);
    k_bsum<<<NB, SCAN_B>>>();
    k_sscan<<<1, 512>>>();
    k_off<<<NB, SCAN_B>>>();
    k_scatter<<<(N_EDGES + 255) / 256, 256>>>(src, dst);
    dim3 aggBlock(12, 16);
    k_agg<<<(N_NODES + 15) / 16, aggBlock>>>(lin, out);
}

// round 13
// speedup vs baseline: 1.3165x; 1.0523x over previous
#include <cuda_runtime.h>
#include <cuda_bf16.h>

#define N_NODES 100000
#define N_EDGES 1600000
#define F_IN 128
#define N_H 3
#define N_D 16
#define HD 48
#define NEG_SLOPE 0.2f

#define SCAN_B 256
#define NB ((N_NODES + SCAN_B - 1) / SCAN_B)   // 391

#define GB_NODES 128          // nodes per gemm block
#define GB_THREADS 256

// Scratch (device globals)
__device__ float  g_feat[N_NODES * HD];     // projected features (N,48)
__device__ float4 g_el[N_NODES];            // (el0,el1,el2,_)
__device__ float4 g_er[N_NODES];            // (er0,er1,er2,_)
__device__ int    g_esrc[N_EDGES];          // src index per edge, grouped by dst
__device__ unsigned short g_pos[N_EDGES];   // edge rank within its dst segment
__device__ int    g_count[N_NODES];         // in-degree
__device__ int    g_off[N_NODES];           // CSR segment start
__device__ int    g_bsum[NB];               // per-block count sums
__device__ int    g_bbase[NB];              // exclusive scan of block sums

// ---------------------------------------------------------------------------
// Kernel 0: zero degree counters
// ---------------------------------------------------------------------------
__global__ void k_init() {
    int i = blockIdx.x * blockDim.x + threadIdx.x;
    if (i < N_NODES) g_count[i] = 0;
}

// ---------------------------------------------------------------------------
// Kernel 1: register-tiled GEMM, vectorized SMEM reads.
// Thread tile 4 nodes x 6 cols; per k-step 1 LDS.128 + 3 LDS.64 feed 24 FFMA.
// ---------------------------------------------------------------------------
__global__ __launch_bounds__(GB_THREADS) void k_gemm(const float* __restrict__ x,
                                                     const float* __restrict__ W)
{
    __shared__ __align__(16) float Wt[F_IN][HD];      // Wt[k][j] = W[j*F_IN+k]
    __shared__ __align__(16) float Xs[16][GB_NODES];  // one k-chunk of x

    int tid = threadIdx.x;
    for (int i = tid; i < HD * F_IN; i += GB_THREADS) {
        int j = i / F_IN, k = i % F_IN;
        Wt[k][j] = W[i];
    }

    int node_base = blockIdx.x * GB_NODES;
    int ng = tid >> 3;            // node group 0..31 (4 nodes each)
    int cg = tid & 7;             // col group 0..7 (6 cols each)
    int ng4 = ng * 4;
    int cg6 = cg * 6;

    int ln = tid & 127;
    int lk = (tid >> 7) * 8;
    int gnode = node_base + ln;
    bool ldok = (gnode < N_NODES);
    const float* xrow = x + (size_t)gnode * F_IN + lk;

    float acc[4][6];
#pragma unroll
    for (int i = 0; i < 4; i++)
#pragma unroll
        for (int c = 0; c < 6; c++) acc[i][c] = 0.f;

    for (int kk = 0; kk < F_IN; kk += 16) {
        __syncthreads();
        float4 v0 = ldok ? *(const float4*)(xrow + kk)     : make_float4(0.f,0.f,0.f,0.f);
        float4 v1 = ldok ? *(const float4*)(xrow + kk + 4) : make_float4(0.f,0.f,0.f,0.f);
        Xs[lk + 0][ln] = v0.x; Xs[lk + 1][ln] = v0.y;
        Xs[lk + 2][ln] = v0.z; Xs[lk + 3][ln] = v0.w;
        Xs[lk + 4][ln] = v1.x; Xs[lk + 5][ln] = v1.y;
        Xs[lk + 6][ln] = v1.z; Xs[lk + 7][ln] = v1.w;
        __syncthreads();

#pragma unroll
        for (int k = 0; k < 16; k++) {
            float4 a = *(const float4*)&Xs[k][ng4];            // LDS.128, bcast
            const float2* wr = (const float2*)&Wt[kk + k][cg6];
            float2 w01 = wr[0];
            float2 w23 = wr[1];
            float2 w45 = wr[2];
            acc[0][0] = fmaf(a.x, w01.x, acc[0][0]); acc[0][1] = fmaf(a.x, w01.y, acc[0][1]);
            acc[0][2] = fmaf(a.x, w23.x, acc[0][2]); acc[0][3] = fmaf(a.x, w23.y, acc[0][3]);
            acc[0][4] = fmaf(a.x, w45.x, acc[0][4]); acc[0][5] = fmaf(a.x, w45.y, acc[0][5]);
            acc[1][0] = fmaf(a.y, w01.x, acc[1][0]); acc[1][1] = fmaf(a.y, w01.y, acc[1][1]);
            acc[1][2] = fmaf(a.y, w23.x, acc[1][2]); acc[1][3] = fmaf(a.y, w23.y, acc[1][3]);
            acc[1][4] = fmaf(a.y, w45.x, acc[1][4]); acc[1][5] = fmaf(a.y, w45.y, acc[1][5]);
            acc[2][0] = fmaf(a.z, w01.x, acc[2][0]); acc[2][1] = fmaf(a.z, w01.y, acc[2][1]);
            acc[2][2] = fmaf(a.z, w23.x, acc[2][2]); acc[2][3] = fmaf(a.z, w23.y, acc[2][3]);
            acc[2][4] = fmaf(a.z, w45.x, acc[2][4]); acc[2][5] = fmaf(a.z, w45.y, acc[2][5]);
            acc[3][0] = fmaf(a.w, w01.x, acc[3][0]); acc[3][1] = fmaf(a.w, w01.y, acc[3][1]);
            acc[3][2] = fmaf(a.w, w23.x, acc[3][2]); acc[3][3] = fmaf(a.w, w23.y, acc[3][3]);
            acc[3][4] = fmaf(a.w, w45.x, acc[3][4]); acc[3][5] = fmaf(a.w, w45.y, acc[3][5]);
        }
    }

#pragma unroll
    for (int i = 0; i < 4; i++) {
        int n = node_base + ng4 + i;
        if (n < N_NODES) {
            float* dstp = g_feat + (size_t)n * HD + cg6;
            *(float2*)(dstp + 0) = make_float2(acc[i][0], acc[i][1]);
            *(float2*)(dstp + 2) = make_float2(acc[i][2], acc[i][3]);
            *(float2*)(dstp + 4) = make_float2(acc[i][4], acc[i][5]);
        }
    }
}

// ---------------------------------------------------------------------------
// Kernel 1b: attention logits el/er per node (reads freshly-written g_feat).
// ---------------------------------------------------------------------------
__global__ __launch_bounds__(256) void k_logits(const float* __restrict__ al,
                                                const float* __restrict__ ar)
{
    __shared__ float als[HD], ars[HD];
    if (threadIdx.x < HD) {
        als[threadIdx.x] = al[threadIdx.x];
        ars[threadIdx.x] = ar[threadIdx.x];
    }
    __syncthreads();

    int n = blockIdx.x * 256 + threadIdx.x;
    if (n >= N_NODES) return;

    const float4* f4 = (const float4*)(g_feat + (size_t)n * HD);
    float el[N_H] = {0.f, 0.f, 0.f};
    float er[N_H] = {0.f, 0.f, 0.f};
#pragma unroll
    for (int q = 0; q < HD / 4; q++) {
        float4 f = f4[q];
        int j = 4 * q;
        int h = j >> 4;
        el[h] = fmaf(f.x, als[j], fmaf(f.y, als[j+1], fmaf(f.z, als[j+2], fmaf(f.w, als[j+3], el[h]))));
        er[h] = fmaf(f.x, ars[j], fmaf(f.y, ars[j+1], fmaf(f.z, ars[j+2], fmaf(f.w, ars[j+3], er[h]))));
    }
    g_el[n] = make_float4(el[0], el[1], el[2], 0.f);
    g_er[n] = make_float4(er[0], er[1], er[2], 0.f);
}

// ---------------------------------------------------------------------------
// Kernel 2: in-degree histogram. The atomic's return value IS the edge's
// rank within its dst segment — store it so scatter needs no atomic.
// ---------------------------------------------------------------------------
__global__ void k_hist(const int* __restrict__ dst) {
    int e = blockIdx.x * blockDim.x + threadIdx.x;
    if (e >= N_EDGES) return;
    int p = atomicAdd(&g_count[dst[e]], 1);
    g_pos[e] = (unsigned short)p;
}

// ---------------------------------------------------------------------------
// Kernel 3a/3b/3c: hierarchical exclusive scan of g_count -> g_off
// ---------------------------------------------------------------------------
__global__ __launch_bounds__(SCAN_B) void k_bsum() {
    __shared__ int sh[SCAN_B];
    int i = blockIdx.x * SCAN_B + threadIdx.x;
    sh[threadIdx.x] = (i < N_NODES) ? g_count[i] : 0;
    __syncthreads();
    for (int off = SCAN_B / 2; off > 0; off >>= 1) {
        if (threadIdx.x < off) sh[threadIdx.x] += sh[threadIdx.x + off];
        __syncthreads();
    }
    if (threadIdx.x == 0) g_bsum[blockIdx.x] = sh[0];
}

__global__ __launch_bounds__(512) void k_sscan() {
    __shared__ int sh[512];
    int t = threadIdx.x;
    sh[t] = (t < NB) ? g_bsum[t] : 0;
    __syncthreads();
    for (int off = 1; off < 512; off <<= 1) {
        int v = (t >= off) ? sh[t - off] : 0;
        __syncthreads();
        sh[t] += v;
        __syncthreads();
    }
    if (t < NB) g_bbase[t] = (t == 0) ? 0 : sh[t - 1];
}

__global__ __launch_bounds__(SCAN_B) void k_off() {
    __shared__ int sh[SCAN_B];
    int i = blockIdx.x * SCAN_B + threadIdx.x;
    int t = threadIdx.x;
    int c = (i < N_NODES) ? g_count[i] : 0;
    sh[t] = c;
    __syncthreads();
    for (int off = 1; off < SCAN_B; off <<= 1) {
        int v = (t >= off) ? sh[t - off] : 0;
        __syncthreads();
        sh[t] += v;
        __syncthreads();
    }
    if (i < N_NODES) {
        g_off[i] = g_bbase[blockIdx.x] + sh[t] - c;
    }
}

// ---------------------------------------------------------------------------
// Kernel 4: edge scatter — atomic-free, 4B payload. pos = off[d] + rank.
// ---------------------------------------------------------------------------
__global__ void k_scatter(const int* __restrict__ src, const int* __restrict__ dst) {
    int e = blockIdx.x * blockDim.x + threadIdx.x;
    if (e >= N_EDGES) return;
    int d = dst[e];
    int pos = g_off[d] + (int)g_pos[e];
    g_esrc[pos] = src[e];
}

// ---------------------------------------------------------------------------
// Kernel 5: per-dst aggregation, 12 threads/node, float4 gathers.
// Attention recomputed in-loop: a = exp(leakyrelu(el[s].h + er[d].h)).
// er[d] is loop-invariant; el[s] is a broadcast gather; exp is cheap MUFU.
// Max-subtraction skipped: |e| <= ~4, softmax shift-invariant (fp32-safe).
// ---------------------------------------------------------------------------
__global__ __launch_bounds__(192) void k_agg(const float* __restrict__ lin,
                                             float* __restrict__ out) {
    int d = blockIdx.x * 16 + threadIdx.y;
    if (d >= N_NODES) return;
    int tx = threadIdx.x;       // 0..11
    int c4 = tx * 4;            // col base 0,4,...,44
    int h = tx >> 2;            // head 0..2

    int beg = g_off[d];
    int cnt = g_count[d];
    int end = beg + cnt;

    float4 R4 = g_er[d];
    float er_h = (h == 0) ? R4.x : ((h == 1) ? R4.y : R4.z);

    float4 num0 = make_float4(0.f, 0.f, 0.f, 0.f);
    float4 num1 = make_float4(0.f, 0.f, 0.f, 0.f);
    float den0 = 0.f, den1 = 0.f;

    int p = beg;
    for (; p + 2 <= end; p += 2) {
        int s0 = g_esrc[p];
        int s1 = g_esrc[p + 1];
        float4 L0 = g_el[s0];
        float4 L1 = g_el[s1];
        float4 f0 = *(const float4*)(g_feat + (size_t)s0 * HD + c4);
        float4 f1 = *(const float4*)(g_feat + (size_t)s1 * HD + c4);
        float v0 = ((h == 0) ? L0.x : ((h == 1) ? L0.y : L0.z)) + er_h;
        float v1 = ((h == 0) ? L1.x : ((h == 1) ? L1.y : L1.z)) + er_h;
        v0 = v0 > 0.f ? v0 : NEG_SLOPE * v0;
        v1 = v1 > 0.f ? v1 : NEG_SLOPE * v1;
        float a0 = __expf(v0);
        float a1 = __expf(v1);
        num0.x = fmaf(a0, f0.x, num0.x); num0.y = fmaf(a0, f0.y, num0.y);
        num0.z = fmaf(a0, f0.z, num0.z); num0.w = fmaf(a0, f0.w, num0.w);
        den0 += a0;
        num1.x = fmaf(a1, f1.x, num1.x); num1.y = fmaf(a1, f1.y, num1.y);
        num1.z = fmaf(a1, f1.z, num1.z); num1.w = fmaf(a1, f1.w, num1.w);
        den1 += a1;
    }
    if (p < end) {
        int s = g_esrc[p];
        float4 L = g_el[s];
        float4 f = *(const float4*)(g_feat + (size_t)s * HD + c4);
        float v = ((h == 0) ? L.x : ((h == 1) ? L.y : L.z)) + er_h;
        v = v > 0.f ? v : NEG_SLOPE * v;
        float a = __expf(v);
        num0.x = fmaf(a, f.x, num0.x); num0.y = fmaf(a, f.y, num0.y);
        num0.z = fmaf(a, f.z, num0.z); num0.w = fmaf(a, f.w, num0.w);
        den0 += a;
    }

    float den = den0 + den1;
    float inv = (cnt > 0) ? (1.f / den) : 0.f;
    float l = lin[d];
    float4 fd = *(const float4*)(g_feat + (size_t)d * HD + c4);
    float4 r;
    r.x = (1.f - l) * ((num0.x + num1.x) * inv) + l * fd.x;
    r.y = (1.f - l) * ((num0.y + num1.y) * inv) + l * fd.y;
    r.z = (1.f - l) * ((num0.z + num1.z) * inv) + l * fd.z;
    r.w = (1.f - l) * ((num0.w + num1.w) * inv) + l * fd.w;
    *(float4*)(out + (size_t)d * HD + c4) = r;
}

// ---------------------------------------------------------------------------
extern "C" void kernel_launch(void* const* d_in, const int* in_sizes, int n_in,
                              void* d_out, int out_size) {
    const float* x   = (const float*)d_in[0];
    const float* W   = (const float*)d_in[1];
    const float* al  = (const float*)d_in[2];
    const float* ar  = (const float*)d_in[3];
    const float* lin = (const float*)d_in[4];
    const int*   src = (const int*)d_in[5];
    const int*   dst = (const int*)d_in[6];
    float* out = (float*)d_out;

    k_init<<<(N_NODES + 255) / 256, 256>>>();
    k_gemm<<<(N_NODES + GB_NODES - 1) / GB_NODES, GB_THREADS>>>(x, W);
    k_logits<<<(N_NODES + 255) / 256, 256>>>(al, ar);
    k_hist<<<(N_EDGES + 255) / 256, 256>>>(dst);
    k_bsum<<<NB, SCAN_B>>>();
    k_sscan<<<1, 512>>>();
    k_off<<<NB, SCAN_B>>>();
    k_scatter<<<(N_EDGES + 255) / 256, 256>>>(src, dst);
    dim3 aggBlock(12, 16);
    k_agg<<<(N_NODES + 15) / 16, aggBlock>>>(lin, out);
}